// round 3
// baseline (speedup 1.0000x reference)
#include <cuda_runtime.h>
#include <cstdint>

#define NNODES 100000
#define DEG 16
#define DIM 128
#define NC 256   // combined [z | zi] columns

// ---------------- scratch (no allocation allowed) ----------------
__device__ float g_zzi[(size_t)NNODES * NC];   // [z | zi] per node
__device__ float g_h[(size_t)NNODES * DIM];    // layer-1 output
__device__ float g_WcT[DIM * NC];              // transposed combined weights
__device__ float g_ssrc[NNODES];
__device__ float g_sdst[NNODES];

// ---------------- weight prep: WcT[k][n] = (n<128 ? W_W[n][k] : W_U[n-128][k]) ----------------
__global__ void prep_wct_kernel(const float* __restrict__ W_W,
                                const float* __restrict__ W_U) {
    int idx = blockIdx.x * blockDim.x + threadIdx.x;
    if (idx >= DIM * NC) return;
    int k = idx / NC;
    int n = idx % NC;
    g_WcT[idx] = (n < DIM) ? W_W[n * DIM + k] : W_U[(n - DIM) * DIM + k];
}

// ---------------- SGEMM: C[M x 256] = A[M x 128] @ WcT[128 x 256] ----------------
// BM=128 BN=128 BK=16, 256 threads, 8x8 per-thread tile.
#define BM 128
#define BN 128
#define BKK 16
#define TM 8
#define TN 8

__global__ __launch_bounds__(256, 2)
void sgemm_kernel(const float* __restrict__ Aext, int useG, int M) {
    const float* __restrict__ A = useG ? g_h : Aext;
    const float* __restrict__ B = g_WcT;
    float* __restrict__ C = g_zzi;

    __shared__ float As[BKK][BM];
    __shared__ float Bs[BKK][BN];

    int rowBase = blockIdx.x * BM;
    int colBase = blockIdx.y * BN;
    int tid = threadIdx.x;
    int tRow = tid / 16;   // 0..15
    int tCol = tid % 16;   // 0..15

    float acc[TM][TN];
#pragma unroll
    for (int i = 0; i < TM; i++)
#pragma unroll
        for (int j = 0; j < TN; j++) acc[i][j] = 0.f;

    for (int k0 = 0; k0 < DIM; k0 += BKK) {
        // A tile: 128 rows x 16 cols, store transposed into As[k][m]
        {
            int ar = tid / 4;        // 0..63
            int ac = tid % 4;        // float4 column within BK
#pragma unroll
            for (int r = 0; r < 2; r++) {
                int row = ar + r * 64;
                float4 v = make_float4(0.f, 0.f, 0.f, 0.f);
                int grow = rowBase + row;
                if (grow < M)
                    v = *reinterpret_cast<const float4*>(A + (size_t)grow * DIM + k0 + ac * 4);
                As[ac * 4 + 0][row] = v.x;
                As[ac * 4 + 1][row] = v.y;
                As[ac * 4 + 2][row] = v.z;
                As[ac * 4 + 3][row] = v.w;
            }
        }
        // B tile: 16 rows x 128 cols (coalesced, no transpose)
        {
            int br = tid / 32;       // 0..7
            int bc = tid % 32;       // float4 col
#pragma unroll
            for (int r = 0; r < 2; r++) {
                int row = br + r * 8;
                float4 v = *reinterpret_cast<const float4*>(
                    B + (size_t)(k0 + row) * NC + colBase + bc * 4);
                *reinterpret_cast<float4*>(&Bs[row][bc * 4]) = v;
            }
        }
        __syncthreads();

#pragma unroll
        for (int k = 0; k < BKK; k++) {
            float a_frag[TM], b_frag[TN];
            float4 a0 = *reinterpret_cast<const float4*>(&As[k][tRow * TM]);
            float4 a1 = *reinterpret_cast<const float4*>(&As[k][tRow * TM + 4]);
            a_frag[0] = a0.x; a_frag[1] = a0.y; a_frag[2] = a0.z; a_frag[3] = a0.w;
            a_frag[4] = a1.x; a_frag[5] = a1.y; a_frag[6] = a1.z; a_frag[7] = a1.w;
            float4 b0 = *reinterpret_cast<const float4*>(&Bs[k][tCol * TN]);
            float4 b1 = *reinterpret_cast<const float4*>(&Bs[k][tCol * TN + 4]);
            b_frag[0] = b0.x; b_frag[1] = b0.y; b_frag[2] = b0.z; b_frag[3] = b0.w;
            b_frag[4] = b1.x; b_frag[5] = b1.y; b_frag[6] = b1.z; b_frag[7] = b1.w;
#pragma unroll
            for (int i = 0; i < TM; i++)
#pragma unroll
                for (int j = 0; j < TN; j++)
                    acc[i][j] += a_frag[i] * b_frag[j];
        }
        __syncthreads();
    }

#pragma unroll
    for (int i = 0; i < TM; i++) {
        int row = rowBase + tRow * TM + i;
        if (row < M) {
#pragma unroll
            for (int j = 0; j < TN; j += 4) {
                float4 v = make_float4(acc[i][j], acc[i][j + 1], acc[i][j + 2], acc[i][j + 3]);
                *reinterpret_cast<float4*>(C + (size_t)row * NC + colBase + tCol * TN + j) = v;
            }
        }
    }
}

// ---------------- per-node attention scores: s_src[n]=z[n]·a[0:128], s_dst[n]=z[n]·a[128:256] ----------------
__global__ __launch_bounds__(256)
void scores_kernel(const float* __restrict__ Wa) {
    int warp = (blockIdx.x * blockDim.x + threadIdx.x) >> 5;
    int lane = threadIdx.x & 31;
    if (warp >= NNODES) return;
    float4 z4 = *reinterpret_cast<const float4*>(g_zzi + (size_t)warp * NC + lane * 4);
    float4 as = *reinterpret_cast<const float4*>(Wa + lane * 4);
    float4 ad = *reinterpret_cast<const float4*>(Wa + DIM + lane * 4);
    float ss = z4.x * as.x + z4.y * as.y + z4.z * as.z + z4.w * as.w;
    float sd = z4.x * ad.x + z4.y * ad.y + z4.z * ad.z + z4.w * ad.w;
#pragma unroll
    for (int o = 16; o > 0; o >>= 1) {
        ss += __shfl_xor_sync(0xFFFFFFFFu, ss, o);
        sd += __shfl_xor_sync(0xFFFFFFFFu, sd, o);
    }
    if (lane == 0) {
        g_ssrc[warp] = ss;
        g_sdst[warp] = sd;
    }
}

// ---------------- per-node softmax + gather-aggregate + relu epilogue ----------------
// One warp per node. Edges for node i are contiguous: e = 16*i + k.
__global__ __launch_bounds__(256)
void aggregate_kernel(const float* __restrict__ edge_d,
                      const int* __restrict__ edge_src,
                      const float* __restrict__ W_V,
                      const float* __restrict__ Wa,
                      float* __restrict__ out_ext, int useG) {
    int warp = (blockIdx.x * blockDim.x + threadIdx.x) >> 5;
    int lane = threadIdx.x & 31;
    if (warp >= NNODES) return;
    float* __restrict__ out = useG ? g_h : out_ext;

    float cva = W_V[0] * Wa[2 * DIM];   // t·a_t scalar coefficient
    float sdi = g_sdst[warp];

    int src = 0;
    float e = -1e30f;
    if (lane < DEG) {
        size_t ei = (size_t)warp * DEG + lane;
        src = edge_src[ei];
        e = g_ssrc[src] + sdi + edge_d[ei] * cva;
        e = (e >= 0.f) ? e : 0.01f * e;   // leaky relu
    }
    // max over the 16-lane group (xor offsets 8..1 keep lanes 0-15 isolated)
    float m = e;
#pragma unroll
    for (int o = 8; o > 0; o >>= 1) m = fmaxf(m, __shfl_xor_sync(0xFFFFFFFFu, m, o));
    float ex = (lane < DEG) ? __expf(e - m) : 0.f;
    float s = ex;
#pragma unroll
    for (int o = 8; o > 0; o >>= 1) s += __shfl_xor_sync(0xFFFFFFFFu, s, o);
    float alpha = ex / s;   // valid on lanes 0-15

    float4 acc = make_float4(0.f, 0.f, 0.f, 0.f);
#pragma unroll
    for (int k = 0; k < DEG; k++) {
        int   sk = __shfl_sync(0xFFFFFFFFu, src, k);
        float ak = __shfl_sync(0xFFFFFFFFu, alpha, k);
        float4 z4 = *reinterpret_cast<const float4*>(g_zzi + (size_t)sk * NC + lane * 4);
        acc.x += ak * z4.x;
        acc.y += ak * z4.y;
        acc.z += ak * z4.z;
        acc.w += ak * z4.w;
    }
    float4 zi4 = *reinterpret_cast<const float4*>(g_zzi + (size_t)warp * NC + DIM + lane * 4);
    float4 o4;
    o4.x = fmaxf(zi4.x + acc.x, 0.f);
    o4.y = fmaxf(zi4.y + acc.y, 0.f);
    o4.z = fmaxf(zi4.z + acc.z, 0.f);
    o4.w = fmaxf(zi4.w + acc.w, 0.f);
    *reinterpret_cast<float4*>(out + (size_t)warp * DIM + lane * 4) = o4;
}

// ---------------- launch ----------------
extern "C" void kernel_launch(void* const* d_in, const int* in_sizes, int n_in,
                              void* d_out, int out_size) {
    const float* attr    = (const float*)d_in[0];
    const float* edge_d  = (const float*)d_in[1];
    const float* W_V1    = (const float*)d_in[2];
    const float* W_W1    = (const float*)d_in[3];
    const float* W_U1    = (const float*)d_in[4];
    const float* W_a1    = (const float*)d_in[5];
    const float* W_V2    = (const float*)d_in[6];
    const float* W_W2    = (const float*)d_in[7];
    const float* W_U2    = (const float*)d_in[8];
    const float* W_a2    = (const float*)d_in[9];
    const int*   edge_src = (const int*)d_in[10];
    float* out = (float*)d_out;

    dim3 gemm_grid((NNODES + BM - 1) / BM, NC / BN);
    int warp_blocks = (NNODES * 32 + 255) / 256;

    // ----- layer 1 -----
    prep_wct_kernel<<<(DIM * NC + 255) / 256, 256>>>(W_W1, W_U1);
    sgemm_kernel<<<gemm_grid, 256>>>(attr, 0, NNODES);
    scores_kernel<<<warp_blocks, 256>>>(W_a1);
    aggregate_kernel<<<warp_blocks, 256>>>(edge_d, edge_src, W_V1, W_a1, nullptr, 1);

    // ----- layer 2 -----
    prep_wct_kernel<<<(DIM * NC + 255) / 256, 256>>>(W_W2, W_U2);
    sgemm_kernel<<<gemm_grid, 256>>>(nullptr, 1, NNODES);
    scores_kernel<<<warp_blocks, 256>>>(W_a2);
    aggregate_kernel<<<warp_blocks, 256>>>(edge_d, edge_src, W_V2, W_a2, out, 0);
}

// round 6
// speedup vs baseline: 1.4807x; 1.4807x over previous
#include <cuda_runtime.h>
#include <cuda_bf16.h>
#include <cstdint>

#define NNODES 100000
#define DEG 16
#define DIM 128
#define NC 256

// ---------------- scratch (no allocation allowed) ----------------
__device__ float g_zzi[(size_t)NNODES * NC];                 // [z | zi] fp32
__device__ __nv_bfloat16 g_Ah[(size_t)NNODES * DIM];         // A hi (GEMM input)
__device__ __nv_bfloat16 g_Al[(size_t)NNODES * DIM];         // A lo
__device__ __nv_bfloat16 g_Bh[NC * DIM];                     // combined weights hi [256 x 128] K-contiguous
__device__ __nv_bfloat16 g_Bl[NC * DIM];                     // combined weights lo
__device__ float g_ssrc[NNODES];
__device__ float g_sdst[NNODES];

__device__ __forceinline__ uint32_t smem_u32(const void* p) {
    uint32_t a;
    asm("{ .reg .u64 t; cvta.to.shared.u64 t, %1; cvt.u32.u64 %0, t; }" : "=r"(a) : "l"(p));
    return a;
}

__device__ __forceinline__ void split_bf16(float x, __nv_bfloat16& h, __nv_bfloat16& l) {
    h = __float2bfloat16(x);
    l = __float2bfloat16(x - __bfloat162float(h));
}

// ---------------- weight prep ----------------
__global__ void prep_w_kernel(const float* __restrict__ W_W, const float* __restrict__ W_U) {
    int idx = blockIdx.x * blockDim.x + threadIdx.x;
    if (idx >= NC * DIM) return;
    float v = (idx < DIM * DIM) ? W_W[idx] : W_U[idx - DIM * DIM];
    __nv_bfloat16 h, l;
    split_bf16(v, h, l);
    g_Bh[idx] = h;
    g_Bl[idx] = l;
}

// ---------------- attr -> bf16 hi/lo ----------------
__global__ __launch_bounds__(256) void conv_attr_kernel(const float* __restrict__ attr) {
    int gid = blockIdx.x * blockDim.x + threadIdx.x;
    if (gid >= NNODES * DIM / 4) return;
    float4 v = reinterpret_cast<const float4*>(attr)[gid];
    __nv_bfloat16 hh[4], ll[4];
    split_bf16(v.x, hh[0], ll[0]);
    split_bf16(v.y, hh[1], ll[1]);
    split_bf16(v.z, hh[2], ll[2]);
    split_bf16(v.w, hh[3], ll[3]);
    reinterpret_cast<uint2*>(g_Ah)[gid] = *reinterpret_cast<uint2*>(hh);
    reinterpret_cast<uint2*>(g_Al)[gid] = *reinterpret_cast<uint2*>(ll);
}

// ---------------- mma.sync GEMM: C[M x 256] = A[M x 128] @ Wc^T, 3-pass bf16 split ----------------
// Smem tiles padded to 272 B/row (17x16B chunks) for conflict-free ldmatrix.
#define TPITCH 272
#define TILE_SM (128 * TPITCH)          // 34816 B per bf16 tile
#define CPITCH 132                      // fp32 epilogue staging pitch (floats)
#define SMEM_DYN (4 * TILE_SM)          // 139264 B  (C staging reuses tile 0/1)

__device__ __forceinline__ void load_tile(uint32_t sm_dst, const __nv_bfloat16* __restrict__ gptr,
                                          int rowBase, int maxRows, int tid) {
#pragma unroll
    for (int it = 0; it < 8; it++) {
        int chunk = tid + it * 256;       // 2048 chunks of 16B
        int row = chunk >> 4;
        int c8  = chunk & 15;
        uint4 v = make_uint4(0u, 0u, 0u, 0u);
        int grow = rowBase + row;
        if (grow < maxRows)
            v = *reinterpret_cast<const uint4*>(gptr + (size_t)grow * DIM + c8 * 8);
        asm volatile("st.shared.v4.b32 [%0], {%1,%2,%3,%4};"
                     :: "r"(sm_dst + row * TPITCH + c8 * 16),
                        "r"(v.x), "r"(v.y), "r"(v.z), "r"(v.w) : "memory");
    }
}

__device__ __forceinline__ void ldsm_x4(uint32_t* r, uint32_t addr) {
    asm volatile("ldmatrix.sync.aligned.m8n8.x4.shared.b16 {%0,%1,%2,%3}, [%4];"
                 : "=r"(r[0]), "=r"(r[1]), "=r"(r[2]), "=r"(r[3]) : "r"(addr));
}
__device__ __forceinline__ void mma_bf16(float* d, const uint32_t* a, const uint32_t* b) {
    asm volatile("mma.sync.aligned.m16n8k16.row.col.f32.bf16.bf16.f32 "
                 "{%0,%1,%2,%3}, {%4,%5,%6,%7}, {%8,%9}, {%0,%1,%2,%3};"
                 : "+f"(d[0]), "+f"(d[1]), "+f"(d[2]), "+f"(d[3])
                 : "r"(a[0]), "r"(a[1]), "r"(a[2]), "r"(a[3]), "r"(b[0]), "r"(b[1]));
}

__global__ __launch_bounds__(256, 1)
void mma_gemm_kernel(int M) {
    extern __shared__ char dynsmem[];
    uint32_t s0 = smem_u32(dynsmem);
    const uint32_t SM_AH = s0;
    const uint32_t SM_AL = s0 + TILE_SM;
    const uint32_t SM_BH = s0 + 2 * TILE_SM;
    const uint32_t SM_BL = s0 + 3 * TILE_SM;
    const uint32_t SM_C  = s0;                 // reuse A region after mainloop

    int tid  = threadIdx.x;
    int wid  = tid >> 5;
    int lane = tid & 31;
    int warpM = (wid & 3) * 32;                // 4 warps along M: 32 rows each
    int warpN = (wid >> 2) * 64;               // 2 warps along N: 64 cols each
    int rowBase = blockIdx.x * 128;
    int nBase   = blockIdx.y * 128;

    load_tile(SM_AH, g_Ah, rowBase, M, tid);
    load_tile(SM_AL, g_Al, rowBase, M, tid);
    load_tile(SM_BH, g_Bh + (size_t)nBase * DIM, 0, 1 << 30, tid);
    load_tile(SM_BL, g_Bl + (size_t)nBase * DIM, 0, 1 << 30, tid);
    __syncthreads();

    float acc[2][8][4];
#pragma unroll
    for (int mi = 0; mi < 2; mi++)
#pragma unroll
        for (int ni = 0; ni < 8; ni++)
#pragma unroll
            for (int j = 0; j < 4; j++) acc[mi][ni][j] = 0.f;

    // ldmatrix per-lane offsets
    int aRow = (lane & 15);                    // + mi*16 + warpM
    int aK   = (lane >> 4) << 3;               // 0 or 8
    int bRow = (lane & 7) + ((lane >> 4) << 3);// + ni*16 + warpN
    int bK   = ((lane >> 3) & 1) << 3;         // 0 or 8

#pragma unroll
    for (int pass = 0; pass < 3; pass++) {
        uint32_t Asm = (pass == 2) ? SM_AL : SM_AH;
        uint32_t Bsm = (pass == 1) ? SM_BL : SM_BH;
#pragma unroll
        for (int ks = 0; ks < 8; ks++) {
            int k0 = ks * 16;
            uint32_t a[2][4];
#pragma unroll
            for (int mi = 0; mi < 2; mi++)
                ldsm_x4(a[mi], Asm + (warpM + mi * 16 + aRow) * TPITCH + (k0 + aK) * 2);
            uint32_t b[8][2];
#pragma unroll
            for (int nq = 0; nq < 4; nq++) {
                uint32_t r[4];
                ldsm_x4(r, Bsm + (warpN + nq * 16 + bRow) * TPITCH + (k0 + bK) * 2);
                b[nq * 2 + 0][0] = r[0]; b[nq * 2 + 0][1] = r[1];
                b[nq * 2 + 1][0] = r[2]; b[nq * 2 + 1][1] = r[3];
            }
#pragma unroll
            for (int mi = 0; mi < 2; mi++)
#pragma unroll
                for (int ni = 0; ni < 8; ni++)
                    mma_bf16(acc[mi][ni], a[mi], b[ni]);
        }
    }

    __syncthreads();   // done reading A/B tiles; reuse smem for C staging

    // stage C in smem (fp32, pitch 132 floats) for coalesced global stores
    int qrow = lane >> 2;            // 0..7
    int qcol = (lane & 3) * 2;
#pragma unroll
    for (int mi = 0; mi < 2; mi++)
#pragma unroll
        for (int ni = 0; ni < 8; ni++) {
            int r0 = warpM + mi * 16 + qrow;
            int c0 = warpN + ni * 8 + qcol;
            uint32_t addr = SM_C + (uint32_t)(r0 * CPITCH + c0) * 4u;
            asm volatile("st.shared.v2.f32 [%0], {%1,%2};"
                         :: "r"(addr), "f"(acc[mi][ni][0]), "f"(acc[mi][ni][1]) : "memory");
            asm volatile("st.shared.v2.f32 [%0], {%1,%2};"
                         :: "r"(addr + 8u * CPITCH * 4u), "f"(acc[mi][ni][2]), "f"(acc[mi][ni][3]) : "memory");
        }
    __syncthreads();

#pragma unroll
    for (int it = 0; it < 16; it++) {
        int idx = tid + it * 256;        // 4096 float4s
        int row = idx >> 5;
        int c4  = idx & 31;
        int grow = rowBase + row;
        if (grow < M) {
            float4 v;
            asm volatile("ld.shared.v4.f32 {%0,%1,%2,%3}, [%4];"
                         : "=f"(v.x), "=f"(v.y), "=f"(v.z), "=f"(v.w)
                         : "r"(SM_C + (uint32_t)(row * CPITCH + c4 * 4) * 4u));
            *reinterpret_cast<float4*>(g_zzi + (size_t)grow * NC + nBase + c4 * 4) = v;
        }
    }
}

// ---------------- per-node attention scores ----------------
__global__ __launch_bounds__(256)
void scores_kernel(const float* __restrict__ Wa) {
    int warp = (blockIdx.x * blockDim.x + threadIdx.x) >> 5;
    int lane = threadIdx.x & 31;
    if (warp >= NNODES) return;
    float4 z4 = *reinterpret_cast<const float4*>(g_zzi + (size_t)warp * NC + lane * 4);
    float4 as = *reinterpret_cast<const float4*>(Wa + lane * 4);
    float4 ad = *reinterpret_cast<const float4*>(Wa + DIM + lane * 4);
    float ss = z4.x * as.x + z4.y * as.y + z4.z * as.z + z4.w * as.w;
    float sd = z4.x * ad.x + z4.y * ad.y + z4.z * ad.z + z4.w * ad.w;
#pragma unroll
    for (int o = 16; o > 0; o >>= 1) {
        ss += __shfl_xor_sync(0xFFFFFFFFu, ss, o);
        sd += __shfl_xor_sync(0xFFFFFFFFu, sd, o);
    }
    if (lane == 0) {
        g_ssrc[warp] = ss;
        g_sdst[warp] = sd;
    }
}

// ---------------- per-node softmax + gather-aggregate + relu epilogue ----------------
__global__ __launch_bounds__(256)
void aggregate_kernel(const float* __restrict__ edge_d,
                      const int* __restrict__ edge_src,
                      const float* __restrict__ W_V,
                      const float* __restrict__ Wa,
                      float* __restrict__ out_ext, int toBf16) {
    int warp = (blockIdx.x * blockDim.x + threadIdx.x) >> 5;
    int lane = threadIdx.x & 31;
    if (warp >= NNODES) return;

    float cva = W_V[0] * Wa[2 * DIM];
    float sdi = g_sdst[warp];

    int src = 0;
    float e = -1e30f;
    if (lane < DEG) {
        size_t ei = (size_t)warp * DEG + lane;
        src = edge_src[ei];
        e = g_ssrc[src] + sdi + edge_d[ei] * cva;
        e = (e >= 0.f) ? e : 0.01f * e;
    }
    float m = e;
#pragma unroll
    for (int o = 8; o > 0; o >>= 1) m = fmaxf(m, __shfl_xor_sync(0xFFFFFFFFu, m, o));
    float ex = (lane < DEG) ? __expf(e - m) : 0.f;
    float s = ex;
#pragma unroll
    for (int o = 8; o > 0; o >>= 1) s += __shfl_xor_sync(0xFFFFFFFFu, s, o);
    float alpha = ex / s;

    float4 acc = make_float4(0.f, 0.f, 0.f, 0.f);
#pragma unroll
    for (int k = 0; k < DEG; k++) {
        int   sk = __shfl_sync(0xFFFFFFFFu, src, k);
        float ak = __shfl_sync(0xFFFFFFFFu, alpha, k);
        float4 z4 = *reinterpret_cast<const float4*>(g_zzi + (size_t)sk * NC + lane * 4);
        acc.x += ak * z4.x;
        acc.y += ak * z4.y;
        acc.z += ak * z4.z;
        acc.w += ak * z4.w;
    }
    float4 zi4 = *reinterpret_cast<const float4*>(g_zzi + (size_t)warp * NC + DIM + lane * 4);
    float4 o4;
    o4.x = fmaxf(zi4.x + acc.x, 0.f);
    o4.y = fmaxf(zi4.y + acc.y, 0.f);
    o4.z = fmaxf(zi4.z + acc.z, 0.f);
    o4.w = fmaxf(zi4.w + acc.w, 0.f);

    if (toBf16) {
        __nv_bfloat16 hh[4], ll[4];
        split_bf16(o4.x, hh[0], ll[0]);
        split_bf16(o4.y, hh[1], ll[1]);
        split_bf16(o4.z, hh[2], ll[2]);
        split_bf16(o4.w, hh[3], ll[3]);
        size_t base = (size_t)warp * DIM + lane * 4;
        *reinterpret_cast<uint2*>(g_Ah + base) = *reinterpret_cast<uint2*>(hh);
        *reinterpret_cast<uint2*>(g_Al + base) = *reinterpret_cast<uint2*>(ll);
    } else {
        *reinterpret_cast<float4*>(out_ext + (size_t)warp * DIM + lane * 4) = o4;
    }
}

// ---------------- launch ----------------
extern "C" void kernel_launch(void* const* d_in, const int* in_sizes, int n_in,
                              void* d_out, int out_size) {
    const float* attr    = (const float*)d_in[0];
    const float* edge_d  = (const float*)d_in[1];
    const float* W_V1    = (const float*)d_in[2];
    const float* W_W1    = (const float*)d_in[3];
    const float* W_U1    = (const float*)d_in[4];
    const float* W_a1    = (const float*)d_in[5];
    const float* W_V2    = (const float*)d_in[6];
    const float* W_W2    = (const float*)d_in[7];
    const float* W_U2    = (const float*)d_in[8];
    const float* W_a2    = (const float*)d_in[9];
    const int*   edge_src = (const int*)d_in[10];
    float* out = (float*)d_out;

    static int smem_set = 0;
    if (!smem_set) {
        cudaFuncSetAttribute(mma_gemm_kernel, cudaFuncAttributeMaxDynamicSharedMemorySize, SMEM_DYN);
        smem_set = 1;
    }

    dim3 gemm_grid((NNODES + 127) / 128, 2);
    int warp_blocks = (NNODES * 32 + 255) / 256;

    // ----- layer 1 -----
    prep_w_kernel<<<(NC * DIM + 255) / 256, 256>>>(W_W1, W_U1);
    conv_attr_kernel<<<(NNODES * DIM / 4 + 255) / 256, 256>>>(attr);
    mma_gemm_kernel<<<gemm_grid, 256, SMEM_DYN>>>(NNODES);
    scores_kernel<<<warp_blocks, 256>>>(W_a1);
    aggregate_kernel<<<warp_blocks, 256>>>(edge_d, edge_src, W_V1, W_a1, nullptr, 1);

    // ----- layer 2 -----
    prep_w_kernel<<<(NC * DIM + 255) / 256, 256>>>(W_W2, W_U2);
    mma_gemm_kernel<<<gemm_grid, 256, SMEM_DYN>>>(NNODES);
    scores_kernel<<<warp_blocks, 256>>>(W_a2);
    aggregate_kernel<<<warp_blocks, 256>>>(edge_d, edge_src, W_V2, W_a2, out, 0);
}

// round 7
// speedup vs baseline: 1.6584x; 1.1200x over previous
#include <cuda_runtime.h>
#include <cuda_bf16.h>
#include <cuda_fp16.h>
#include <cstdint>

#define NNODES 100000
#define DEG 16
#define DIM 128
#define NC 256

// ---------------- scratch (no allocation allowed) ----------------
__device__ __half g_zh[(size_t)NNODES * DIM];                // z in fp16 (gather source)
__device__ float g_zi[(size_t)NNODES * DIM];                 // z_i fp32
__device__ __nv_bfloat16 g_Ah[(size_t)NNODES * DIM];         // layer-2 GEMM input hi
__device__ __nv_bfloat16 g_Al[(size_t)NNODES * DIM];         // layer-2 GEMM input lo
__device__ __nv_bfloat16 g_Bh[NC * DIM];                     // combined weights hi [256 x 128] K-contiguous
__device__ __nv_bfloat16 g_Bl[NC * DIM];                     // combined weights lo
__device__ float g_ssrc[NNODES];
__device__ float g_sdst[NNODES];

__device__ __forceinline__ uint32_t smem_u32(const void* p) {
    uint32_t a;
    asm("{ .reg .u64 t; cvta.to.shared.u64 t, %1; cvt.u32.u64 %0, t; }" : "=r"(a) : "l"(p));
    return a;
}

__device__ __forceinline__ void split_bf16(float x, __nv_bfloat16& h, __nv_bfloat16& l) {
    h = __float2bfloat16(x);
    l = __float2bfloat16(x - __bfloat162float(h));
}

// ---------------- weight prep ----------------
__global__ void prep_w_kernel(const float* __restrict__ W_W, const float* __restrict__ W_U) {
    int idx = blockIdx.x * blockDim.x + threadIdx.x;
    if (idx >= NC * DIM) return;
    float v = (idx < DIM * DIM) ? W_W[idx] : W_U[idx - DIM * DIM];
    __nv_bfloat16 h, l;
    split_bf16(v, h, l);
    g_Bh[idx] = h;
    g_Bl[idx] = l;
}

// ---------------- mma.sync GEMM: [z | zi] = A[M x 128] @ Wc^T, 3-pass bf16 split ----------------
// Smem tiles padded to 272 B/row (17x16B chunks) for conflict-free ldmatrix.
#define TPITCH 272
#define TILE_SM (128 * TPITCH)          // 34816 B per bf16 tile
#define CPITCH 132                      // fp32 epilogue staging pitch (floats)
#define SMEM_DYN (4 * TILE_SM)          // 139264 B  (C staging reuses tiles 0/1)

__device__ __forceinline__ void load_tile_bf16(uint32_t sm_dst, const __nv_bfloat16* __restrict__ gptr,
                                               int rowBase, int maxRows, int tid) {
#pragma unroll
    for (int it = 0; it < 8; it++) {
        int chunk = tid + it * 256;       // 2048 chunks of 16B
        int row = chunk >> 4;
        int c8  = chunk & 15;
        uint4 v = make_uint4(0u, 0u, 0u, 0u);
        int grow = rowBase + row;
        if (grow < maxRows)
            v = *reinterpret_cast<const uint4*>(gptr + (size_t)grow * DIM + c8 * 8);
        asm volatile("st.shared.v4.b32 [%0], {%1,%2,%3,%4};"
                     :: "r"(sm_dst + row * TPITCH + c8 * 16),
                        "r"(v.x), "r"(v.y), "r"(v.z), "r"(v.w) : "memory");
    }
}

// fp32 source: split hi/lo while loading (replaces the separate conv kernel)
__device__ __forceinline__ void load_tile_fp32split(uint32_t sm_hi, uint32_t sm_lo,
                                                    const float* __restrict__ gptr,
                                                    int rowBase, int maxRows, int tid) {
#pragma unroll
    for (int it = 0; it < 8; it++) {
        int chunk = tid + it * 256;       // 2048 chunks of 8 floats
        int row = chunk >> 4;
        int c8  = chunk & 15;
        float f[8] = {0.f, 0.f, 0.f, 0.f, 0.f, 0.f, 0.f, 0.f};
        int grow = rowBase + row;
        if (grow < maxRows) {
            const float4* p = reinterpret_cast<const float4*>(gptr + (size_t)grow * DIM + c8 * 8);
            float4 v0 = p[0], v1 = p[1];
            f[0] = v0.x; f[1] = v0.y; f[2] = v0.z; f[3] = v0.w;
            f[4] = v1.x; f[5] = v1.y; f[6] = v1.z; f[7] = v1.w;
        }
        __nv_bfloat16 hh[8], ll[8];
#pragma unroll
        for (int j = 0; j < 8; j++) split_bf16(f[j], hh[j], ll[j]);
        uint4 vh = *reinterpret_cast<uint4*>(hh);
        uint4 vl = *reinterpret_cast<uint4*>(ll);
        uint32_t off = (uint32_t)(row * TPITCH + c8 * 16);
        asm volatile("st.shared.v4.b32 [%0], {%1,%2,%3,%4};"
                     :: "r"(sm_hi + off), "r"(vh.x), "r"(vh.y), "r"(vh.z), "r"(vh.w) : "memory");
        asm volatile("st.shared.v4.b32 [%0], {%1,%2,%3,%4};"
                     :: "r"(sm_lo + off), "r"(vl.x), "r"(vl.y), "r"(vl.z), "r"(vl.w) : "memory");
    }
}

__device__ __forceinline__ void ldsm_x4(uint32_t* r, uint32_t addr) {
    asm volatile("ldmatrix.sync.aligned.m8n8.x4.shared.b16 {%0,%1,%2,%3}, [%4];"
                 : "=r"(r[0]), "=r"(r[1]), "=r"(r[2]), "=r"(r[3]) : "r"(addr));
}
__device__ __forceinline__ void mma_bf16(float* d, const uint32_t* a, const uint32_t* b) {
    asm volatile("mma.sync.aligned.m16n8k16.row.col.f32.bf16.bf16.f32 "
                 "{%0,%1,%2,%3}, {%4,%5,%6,%7}, {%8,%9}, {%0,%1,%2,%3};"
                 : "+f"(d[0]), "+f"(d[1]), "+f"(d[2]), "+f"(d[3])
                 : "r"(a[0]), "r"(a[1]), "r"(a[2]), "r"(a[3]), "r"(b[0]), "r"(b[1]));
}

__global__ __launch_bounds__(256, 1)
void mma_gemm_kernel(const float* __restrict__ attr, const float* __restrict__ Wa,
                     int M, int srcFp32) {
    extern __shared__ char dynsmem[];
    uint32_t s0 = smem_u32(dynsmem);
    const uint32_t SM_AH = s0;
    const uint32_t SM_AL = s0 + TILE_SM;
    const uint32_t SM_BH = s0 + 2 * TILE_SM;
    const uint32_t SM_BL = s0 + 3 * TILE_SM;
    const uint32_t SM_C  = s0;                 // reuse A region after mainloop

    int tid  = threadIdx.x;
    int wid  = tid >> 5;
    int lane = tid & 31;
    int warpM = (wid & 3) * 32;                // 4 warps along M
    int warpN = (wid >> 2) * 64;               // 2 warps along N
    int rowBase = blockIdx.x * 128;
    int nBase   = blockIdx.y * 128;            // 0 -> z (fp16 + scores), 128 -> zi (fp32)

    if (srcFp32)
        load_tile_fp32split(SM_AH, SM_AL, attr, rowBase, M, tid);
    else {
        load_tile_bf16(SM_AH, g_Ah, rowBase, M, tid);
        load_tile_bf16(SM_AL, g_Al, rowBase, M, tid);
    }
    load_tile_bf16(SM_BH, g_Bh + (size_t)nBase * DIM, 0, 1 << 30, tid);
    load_tile_bf16(SM_BL, g_Bl + (size_t)nBase * DIM, 0, 1 << 30, tid);
    __syncthreads();

    float acc[2][8][4];
#pragma unroll
    for (int mi = 0; mi < 2; mi++)
#pragma unroll
        for (int ni = 0; ni < 8; ni++)
#pragma unroll
            for (int j = 0; j < 4; j++) acc[mi][ni][j] = 0.f;

    int aRow = (lane & 15);
    int aK   = (lane >> 4) << 3;
    int bRow = (lane & 7) + ((lane >> 4) << 3);
    int bK   = ((lane >> 3) & 1) << 3;

#pragma unroll
    for (int pass = 0; pass < 3; pass++) {
        uint32_t Asm = (pass == 2) ? SM_AL : SM_AH;
        uint32_t Bsm = (pass == 1) ? SM_BL : SM_BH;
#pragma unroll
        for (int ks = 0; ks < 8; ks++) {
            int k0 = ks * 16;
            uint32_t a[2][4];
#pragma unroll
            for (int mi = 0; mi < 2; mi++)
                ldsm_x4(a[mi], Asm + (warpM + mi * 16 + aRow) * TPITCH + (k0 + aK) * 2);
            uint32_t b[8][2];
#pragma unroll
            for (int nq = 0; nq < 4; nq++) {
                uint32_t r[4];
                ldsm_x4(r, Bsm + (warpN + nq * 16 + bRow) * TPITCH + (k0 + bK) * 2);
                b[nq * 2 + 0][0] = r[0]; b[nq * 2 + 0][1] = r[1];
                b[nq * 2 + 1][0] = r[2]; b[nq * 2 + 1][1] = r[3];
            }
#pragma unroll
            for (int mi = 0; mi < 2; mi++)
#pragma unroll
                for (int ni = 0; ni < 8; ni++)
                    mma_bf16(acc[mi][ni], a[mi], b[ni]);
        }
    }

    __syncthreads();   // done reading A/B tiles; reuse smem for C staging

    int qrow = lane >> 2;
    int qcol = (lane & 3) * 2;
#pragma unroll
    for (int mi = 0; mi < 2; mi++)
#pragma unroll
        for (int ni = 0; ni < 8; ni++) {
            int r0 = warpM + mi * 16 + qrow;
            int c0 = warpN + ni * 8 + qcol;
            uint32_t addr = SM_C + (uint32_t)(r0 * CPITCH + c0) * 4u;
            asm volatile("st.shared.v2.f32 [%0], {%1,%2};"
                         :: "r"(addr), "f"(acc[mi][ni][0]), "f"(acc[mi][ni][1]) : "memory");
            asm volatile("st.shared.v2.f32 [%0], {%1,%2};"
                         :: "r"(addr + 8u * CPITCH * 4u), "f"(acc[mi][ni][2]), "f"(acc[mi][ni][3]) : "memory");
        }
    __syncthreads();

    // per-thread fixed column group c4 (constant across iterations)
    int c4 = tid & 31;
    float4 as4 = make_float4(0.f, 0.f, 0.f, 0.f), ad4 = as4;
    if (nBase == 0) {
        as4 = *reinterpret_cast<const float4*>(Wa + c4 * 4);
        ad4 = *reinterpret_cast<const float4*>(Wa + DIM + c4 * 4);
    }

#pragma unroll
    for (int it = 0; it < 16; it++) {
        int idx = tid + it * 256;        // 4096 float4s; one warp = one row per iter
        int row = idx >> 5;
        int grow = rowBase + row;
        bool ok = (grow < M);
        float4 v = make_float4(0.f, 0.f, 0.f, 0.f);
        if (ok)
            asm volatile("ld.shared.v4.f32 {%0,%1,%2,%3}, [%4];"
                         : "=f"(v.x), "=f"(v.y), "=f"(v.z), "=f"(v.w)
                         : "r"(SM_C + (uint32_t)(row * CPITCH + c4 * 4) * 4u));
        if (nBase == 0) {
            // fused attention scores: warp-reduce over the row
            float ss = v.x * as4.x + v.y * as4.y + v.z * as4.z + v.w * as4.w;
            float sd = v.x * ad4.x + v.y * ad4.y + v.z * ad4.z + v.w * ad4.w;
#pragma unroll
            for (int o = 16; o > 0; o >>= 1) {
                ss += __shfl_xor_sync(0xFFFFFFFFu, ss, o);
                sd += __shfl_xor_sync(0xFFFFFFFFu, sd, o);
            }
            if (ok) {
                if (lane == 0) { g_ssrc[grow] = ss; g_sdst[grow] = sd; }
                // z -> fp16
                __half2 h0 = __float22half2_rn(make_float2(v.x, v.y));
                __half2 h1 = __float22half2_rn(make_float2(v.z, v.w));
                uint2 u = make_uint2(*reinterpret_cast<uint32_t*>(&h0), *reinterpret_cast<uint32_t*>(&h1));
                *reinterpret_cast<uint2*>(g_zh + (size_t)grow * DIM + c4 * 4) = u;
            }
        } else if (ok) {
            *reinterpret_cast<float4*>(g_zi + (size_t)grow * DIM + c4 * 4) = v;
        }
    }
}

// ---------------- per-node softmax + fp16 gather-aggregate + relu epilogue ----------------
__global__ __launch_bounds__(256)
void aggregate_kernel(const float* __restrict__ edge_d,
                      const int* __restrict__ edge_src,
                      const float* __restrict__ W_V,
                      const float* __restrict__ Wa,
                      float* __restrict__ out_ext, int toBf16) {
    int warp = (blockIdx.x * blockDim.x + threadIdx.x) >> 5;
    int lane = threadIdx.x & 31;
    if (warp >= NNODES) return;

    float cva = W_V[0] * Wa[2 * DIM];
    float sdi = g_sdst[warp];

    int src = 0;
    float e = -1e30f;
    if (lane < DEG) {
        size_t ei = (size_t)warp * DEG + lane;
        src = edge_src[ei];
        e = g_ssrc[src] + sdi + edge_d[ei] * cva;
        e = (e >= 0.f) ? e : 0.01f * e;
    }
    float m = e;
#pragma unroll
    for (int o = 8; o > 0; o >>= 1) m = fmaxf(m, __shfl_xor_sync(0xFFFFFFFFu, m, o));
    float ex = (lane < DEG) ? __expf(e - m) : 0.f;
    float s = ex;
#pragma unroll
    for (int o = 8; o > 0; o >>= 1) s += __shfl_xor_sync(0xFFFFFFFFu, s, o);
    float alpha = ex / s;

    float4 acc = make_float4(0.f, 0.f, 0.f, 0.f);
#pragma unroll
    for (int k = 0; k < DEG; k++) {
        int   sk = __shfl_sync(0xFFFFFFFFu, src, k);
        float ak = __shfl_sync(0xFFFFFFFFu, alpha, k);
        uint2 u = *reinterpret_cast<const uint2*>(g_zh + (size_t)sk * DIM + lane * 4);
        __half2 h0 = *reinterpret_cast<__half2*>(&u.x);
        __half2 h1 = *reinterpret_cast<__half2*>(&u.y);
        float2 f0 = __half22float2(h0);
        float2 f1 = __half22float2(h1);
        acc.x += ak * f0.x;
        acc.y += ak * f0.y;
        acc.z += ak * f1.x;
        acc.w += ak * f1.y;
    }
    float4 zi4 = *reinterpret_cast<const float4*>(g_zi + (size_t)warp * DIM + lane * 4);
    float4 o4;
    o4.x = fmaxf(zi4.x + acc.x, 0.f);
    o4.y = fmaxf(zi4.y + acc.y, 0.f);
    o4.z = fmaxf(zi4.z + acc.z, 0.f);
    o4.w = fmaxf(zi4.w + acc.w, 0.f);

    if (toBf16) {
        __nv_bfloat16 hh[4], ll[4];
        split_bf16(o4.x, hh[0], ll[0]);
        split_bf16(o4.y, hh[1], ll[1]);
        split_bf16(o4.z, hh[2], ll[2]);
        split_bf16(o4.w, hh[3], ll[3]);
        size_t base = (size_t)warp * DIM + lane * 4;
        *reinterpret_cast<uint2*>(g_Ah + base) = *reinterpret_cast<uint2*>(hh);
        *reinterpret_cast<uint2*>(g_Al + base) = *reinterpret_cast<uint2*>(ll);
    } else {
        *reinterpret_cast<float4*>(out_ext + (size_t)warp * DIM + lane * 4) = o4;
    }
}

// ---------------- launch ----------------
extern "C" void kernel_launch(void* const* d_in, const int* in_sizes, int n_in,
                              void* d_out, int out_size) {
    const float* attr    = (const float*)d_in[0];
    const float* edge_d  = (const float*)d_in[1];
    const float* W_V1    = (const float*)d_in[2];
    const float* W_W1    = (const float*)d_in[3];
    const float* W_U1    = (const float*)d_in[4];
    const float* W_a1    = (const float*)d_in[5];
    const float* W_V2    = (const float*)d_in[6];
    const float* W_W2    = (const float*)d_in[7];
    const float* W_U2    = (const float*)d_in[8];
    const float* W_a2    = (const float*)d_in[9];
    const int*   edge_src = (const int*)d_in[10];
    float* out = (float*)d_out;

    static int smem_set = 0;
    if (!smem_set) {
        cudaFuncSetAttribute(mma_gemm_kernel, cudaFuncAttributeMaxDynamicSharedMemorySize, SMEM_DYN);
        smem_set = 1;
    }

    dim3 gemm_grid((NNODES + 127) / 128, 2);
    int warp_blocks = (NNODES * 32 + 255) / 256;

    // ----- layer 1 -----
    prep_w_kernel<<<(NC * DIM + 255) / 256, 256>>>(W_W1, W_U1);
    mma_gemm_kernel<<<gemm_grid, 256, SMEM_DYN>>>(attr, W_a1, NNODES, 1);
    aggregate_kernel<<<warp_blocks, 256>>>(edge_d, edge_src, W_V1, W_a1, nullptr, 1);

    // ----- layer 2 -----
    prep_w_kernel<<<(NC * DIM + 255) / 256, 256>>>(W_W2, W_U2);
    mma_gemm_kernel<<<gemm_grid, 256, SMEM_DYN>>>(nullptr, W_a2, NNODES, 0);
    aggregate_kernel<<<warp_blocks, 256>>>(edge_d, edge_src, W_V2, W_a2, out, 0);
}